// round 16
// baseline (speedup 1.0000x reference)
#include <cuda_runtime.h>
#include <cuda_bf16.h>
#include <math.h>
#include <stdint.h>

#define BATCH 2
#define SEQ   2048
#define DIM   1024
#define NH    16
#define DKH   64
#define MROWS (BATCH*SEQ)

// ---- scratch (allocation-free rules): bf16 hi/lo split buffers ----
__device__ __nv_bfloat16 g_qh[MROWS * DIM], g_ql[MROWS * DIM];
__device__ __nv_bfloat16 g_kh[MROWS * DIM], g_kl[MROWS * DIM];
__device__ __nv_bfloat16 g_vh[MROWS * DIM], g_vl[MROWS * DIM];
__device__ __nv_bfloat16 g_ch[MROWS * DIM], g_cl[MROWS * DIM];
__device__ __nv_bfloat16 g_xqh[MROWS * DIM], g_xql[MROWS * DIM];  // input splits
__device__ __nv_bfloat16 g_xkh[MROWS * DIM], g_xkl[MROWS * DIM];
__device__ __nv_bfloat16 g_xvh[MROWS * DIM], g_xvl[MROWS * DIM];
__device__ __nv_bfloat16 g_wqh[DIM * DIM], g_wql[DIM * DIM];
__device__ __nv_bfloat16 g_wkh[DIM * DIM], g_wkl[DIM * DIM];
__device__ __nv_bfloat16 g_wvh[DIM * DIM], g_wvl[DIM * DIM];
__device__ __nv_bfloat16 g_woh[DIM * DIM], g_wol[DIM * DIM];

// ===========================================================================
// Baseline-PTX helpers (sm_80+)
// ===========================================================================
__device__ __forceinline__ uint32_t cvta_s(const void* p) {
    uint32_t a;
    asm("{ .reg .u64 t; cvta.to.shared.u64 t, %1; cvt.u32.u64 %0, t; }"
        : "=r"(a) : "l"(p));
    return a;
}
__device__ __forceinline__ void ldm4(uint32_t* r, uint32_t addr) {
    asm volatile("ldmatrix.sync.aligned.m8n8.x4.shared.b16 {%0,%1,%2,%3},[%4];"
        : "=r"(r[0]), "=r"(r[1]), "=r"(r[2]), "=r"(r[3]) : "r"(addr));
}
__device__ __forceinline__ void ldm4t(uint32_t* r, uint32_t addr) {
    asm volatile("ldmatrix.sync.aligned.m8n8.x4.trans.shared.b16 {%0,%1,%2,%3},[%4];"
        : "=r"(r[0]), "=r"(r[1]), "=r"(r[2]), "=r"(r[3]) : "r"(addr));
}
__device__ __forceinline__ void mma16816(float* c, const uint32_t* a,
                                         uint32_t b0, uint32_t b1) {
    asm volatile(
        "mma.sync.aligned.m16n8k16.row.col.f32.bf16.bf16.f32 "
        "{%0,%1,%2,%3},{%4,%5,%6,%7},{%8,%9},{%0,%1,%2,%3};"
        : "+f"(c[0]), "+f"(c[1]), "+f"(c[2]), "+f"(c[3])
        : "r"(a[0]), "r"(a[1]), "r"(a[2]), "r"(a[3]), "r"(b0), "r"(b1));
}
__device__ __forceinline__ void cp16(uint32_t dst, const void* src) {
    asm volatile("cp.async.cg.shared.global [%0], [%1], 16;"
        :: "r"(dst), "l"(src) : "memory");
}
__device__ __forceinline__ void cp_commit() {
    asm volatile("cp.async.commit_group;" ::: "memory");
}
__device__ __forceinline__ void cp_wait0() {
    asm volatile("cp.async.wait_group 0;" ::: "memory");
}
__device__ __forceinline__ void cp_wait1() {
    asm volatile("cp.async.wait_group 1;" ::: "memory");
}
__device__ __forceinline__ float ex2(float x) {
    float y;
    asm("ex2.approx.ftz.f32 %0, %1;" : "=f"(y) : "f"(x));
    return y;
}
__device__ __forceinline__ uint32_t pack_bf2(__nv_bfloat16 a, __nv_bfloat16 b) {
    __nv_bfloat162 t = __halves2bfloat162(a, b);
    return reinterpret_cast<uint32_t&>(t);
}

// ===========================================================================
// Split fp32 -> (bf16 hi, bf16 lo)
// ===========================================================================
__global__ __launch_bounds__(256) void split_bf16(
    const float* __restrict__ x, __nv_bfloat16* __restrict__ hi,
    __nv_bfloat16* __restrict__ lo)
{
    const int i = blockIdx.x * 256 + threadIdx.x;
    float4 v = ((const float4*)x)[i];
    __nv_bfloat16 h0 = __float2bfloat16(v.x);
    __nv_bfloat16 h1 = __float2bfloat16(v.y);
    __nv_bfloat16 h2 = __float2bfloat16(v.z);
    __nv_bfloat16 h3 = __float2bfloat16(v.w);
    __nv_bfloat16 l0 = __float2bfloat16(v.x - __bfloat162float(h0));
    __nv_bfloat16 l1 = __float2bfloat16(v.y - __bfloat162float(h1));
    __nv_bfloat16 l2 = __float2bfloat16(v.z - __bfloat162float(h2));
    __nv_bfloat16 l3 = __float2bfloat16(v.w - __bfloat162float(h3));
    ((__nv_bfloat162*)hi)[i * 2 + 0] = __halves2bfloat162(h0, h1);
    ((__nv_bfloat162*)hi)[i * 2 + 1] = __halves2bfloat162(h2, h3);
    ((__nv_bfloat162*)lo)[i * 2 + 0] = __halves2bfloat162(l0, l1);
    ((__nv_bfloat162*)lo)[i * 2 + 1] = __halves2bfloat162(l2, l3);
}

// ===========================================================================
// GEMM (NT) via mma.sync bf16 split-x3:  C = A @ W^T
// MODE 0: fp32 out + bias.  MODE 1: scaled bf16 hi/lo split out.
// ===========================================================================
#define ROWB   80
#define TILE_B (128*ROWB)
#define STAGE_B (4*TILE_B)
#define GEMM_SMEM (2*STAGE_B)

__device__ __forceinline__ void ld_stage(
    uint32_t sdst, const __nv_bfloat16* __restrict__ Ah,
    const __nv_bfloat16* __restrict__ Al,
    const __nv_bfloat16* __restrict__ Wh,
    const __nv_bfloat16* __restrict__ Wl,
    int m0, int n0, int kb, int tid)
{
    const int r_lo = tid >> 2;
    const int c    = tid & 3;
    const __nv_bfloat16* gsrc[4] = {Ah, Al, Wh, Wl};
    const int rbase[4] = {m0, m0, n0, n0};
#pragma unroll
    for (int t = 0; t < 4; t++) {
#pragma unroll
        for (int half = 0; half < 2; half++) {
            const int r = r_lo + half * 64;
            cp16(sdst + t * TILE_B + r * ROWB + c * 16,
                 gsrc[t] + (size_t)(rbase[t] + r) * DIM + kb + c * 8);
        }
    }
}

template <int MODE>
__global__ __launch_bounds__(256) void gemm_mma_x3(
    const __nv_bfloat16* __restrict__ Ah, const __nv_bfloat16* __restrict__ Al,
    const __nv_bfloat16* __restrict__ Wh, const __nv_bfloat16* __restrict__ Wl,
    const float* __restrict__ bias, float* __restrict__ Cc,
    __nv_bfloat16* __restrict__ Oh, __nv_bfloat16* __restrict__ Ol, float scale)
{
    extern __shared__ __align__(128) char sm[];
    const int tid  = threadIdx.x;
    const int lane = tid & 31;
    const int wid  = tid >> 5;
    const int wm   = wid & 3;
    const int wn   = wid >> 2;
    const int m0 = blockIdx.y * 128;
    const int n0 = blockIdx.x * 128;
    const uint32_t sb = cvta_s(sm);

    float acc[2][8][4];
#pragma unroll
    for (int m = 0; m < 2; m++)
#pragma unroll
        for (int n = 0; n < 8; n++)
#pragma unroll
            for (int j = 0; j < 4; j++) acc[m][n][j] = 0.f;

    const uint32_t aOff = (uint32_t)((wm * 32 + (lane & 15)) * ROWB + ((lane >> 4) << 4));
    const uint32_t bOff = (uint32_t)((wn * 64 + (lane & 7) + ((lane >> 4) << 3)) * ROWB
                                     + ((lane & 8) ? 16 : 0));

    ld_stage(sb, Ah, Al, Wh, Wl, m0, n0, 0, tid);
    cp_commit();

    const int NST = DIM / 32;
    for (int t = 0; t < NST; t++) {
        cp_wait0();
        __syncthreads();
        if (t + 1 < NST) {
            ld_stage(sb + ((t + 1) & 1) * STAGE_B, Ah, Al, Wh, Wl,
                     m0, n0, (t + 1) * 32, tid);
            cp_commit();
        }
        const uint32_t st = sb + (t & 1) * STAGE_B;

#pragma unroll
        for (int kk = 0; kk < 2; kk++) {
            const uint32_t kByte = kk * 32;
            uint32_t ah[2][4], al[2][4];
#pragma unroll
            for (int mf = 0; mf < 2; mf++) {
                ldm4(ah[mf], st + aOff + mf * 16 * ROWB + kByte);
                ldm4(al[mf], st + TILE_B + aOff + mf * 16 * ROWB + kByte);
            }
            uint32_t bh[4][4], bl[4][4];
#pragma unroll
            for (int g = 0; g < 4; g++) {
                ldm4(bh[g], st + 2 * TILE_B + bOff + g * 16 * ROWB + kByte);
                ldm4(bl[g], st + 3 * TILE_B + bOff + g * 16 * ROWB + kByte);
            }
#pragma unroll
            for (int mf = 0; mf < 2; mf++)
#pragma unroll
                for (int g = 0; g < 4; g++)
#pragma unroll
                    for (int s = 0; s < 2; s++) {
                        float* cc = acc[mf][g * 2 + s];
                        mma16816(cc, ah[mf], bh[g][s * 2], bh[g][s * 2 + 1]);
                        mma16816(cc, ah[mf], bl[g][s * 2], bl[g][s * 2 + 1]);
                        mma16816(cc, al[mf], bh[g][s * 2], bh[g][s * 2 + 1]);
                    }
        }
        __syncthreads();
    }

    const int grp = lane >> 2;
    const int tig = lane & 3;
#pragma unroll
    for (int mf = 0; mf < 2; mf++) {
        const int row = m0 + wm * 32 + mf * 16 + grp;
#pragma unroll
        for (int n8 = 0; n8 < 8; n8++) {
            const int col = n0 + wn * 64 + n8 * 8 + tig * 2;
            if (MODE == 0) {
                float2 v0 = make_float2(acc[mf][n8][0], acc[mf][n8][1]);
                float2 v1 = make_float2(acc[mf][n8][2], acc[mf][n8][3]);
                const float2 b = *(const float2*)(bias + col);
                v0.x += b.x; v0.y += b.y; v1.x += b.x; v1.y += b.y;
                *(float2*)(Cc + (size_t)row * DIM + col)       = v0;
                *(float2*)(Cc + (size_t)(row + 8) * DIM + col) = v1;
            } else {
                const float v0 = acc[mf][n8][0] * scale, v1 = acc[mf][n8][1] * scale;
                const float v2 = acc[mf][n8][2] * scale, v3 = acc[mf][n8][3] * scale;
                __nv_bfloat16 h0 = __float2bfloat16(v0), h1 = __float2bfloat16(v1);
                __nv_bfloat16 h2 = __float2bfloat16(v2), h3 = __float2bfloat16(v3);
                __nv_bfloat16 e0 = __float2bfloat16(v0 - __bfloat162float(h0));
                __nv_bfloat16 e1 = __float2bfloat16(v1 - __bfloat162float(h1));
                __nv_bfloat16 e2 = __float2bfloat16(v2 - __bfloat162float(h2));
                __nv_bfloat16 e3 = __float2bfloat16(v3 - __bfloat162float(h3));
                *(__nv_bfloat162*)(Oh + (size_t)row * DIM + col)       = __halves2bfloat162(h0, h1);
                *(__nv_bfloat162*)(Oh + (size_t)(row + 8) * DIM + col) = __halves2bfloat162(h2, h3);
                *(__nv_bfloat162*)(Ol + (size_t)row * DIM + col)       = __halves2bfloat162(e0, e1);
                *(__nv_bfloat162*)(Ol + (size_t)(row + 8) * DIM + col) = __halves2bfloat162(e2, e3);
            }
        }
    }
}

// ===========================================================================
// Flash attention via mma.sync bf16 split-x3 (FA2 register P-reuse).
// CTA: 128 q rows x one (b,h); 8 warps, each owns 16 q rows x full 64-key tile.
// KV tiles of 64 keys, cp.async double-buffered. Scores in log2 domain.
// ===========================================================================
#define FROWB 144                       // 72 bf16 per row (64 data + 8 pad)
#define FQ_B   (128*FROWB)              // 18432
#define FKV_T  (64*FROWB)               // 9216
#define FSTG_B (4*FKV_T)                // 36864
#define FLASH_SMEM (2*FQ_B + 2*FSTG_B)  // 110592

__device__ __forceinline__ void ld_kv(
    uint32_t dst, const __nv_bfloat16* __restrict__ Kh,
    const __nv_bfloat16* __restrict__ Kl,
    const __nv_bfloat16* __restrict__ Vh,
    const __nv_bfloat16* __restrict__ Vl,
    size_t grow, int hcol, int tid)
{
    const __nv_bfloat16* srcs[4] = {Kh, Kl, Vh, Vl};
#pragma unroll
    for (int i = 0; i < 8; i++) {
        const int idx = tid + i * 256;
        const int t   = idx >> 9;
        const int rem = idx & 511;
        const int row = rem >> 3;
        const int c   = rem & 7;
        cp16(dst + t * FKV_T + row * FROWB + c * 16,
             srcs[t] + (grow + row) * DIM + hcol + c * 8);
    }
}

__global__ __launch_bounds__(256) void flash_mma(
    const __nv_bfloat16* __restrict__ Qh, const __nv_bfloat16* __restrict__ Ql,
    const __nv_bfloat16* __restrict__ Kh, const __nv_bfloat16* __restrict__ Kl,
    const __nv_bfloat16* __restrict__ Vh, const __nv_bfloat16* __restrict__ Vl,
    __nv_bfloat16* __restrict__ Ch, __nv_bfloat16* __restrict__ Cl)
{
    extern __shared__ __align__(128) char sm[];
    const int tid  = threadIdx.x;
    const int lane = tid & 31;
    const int wid  = tid >> 5;
    const int q0   = blockIdx.x * 128;
    const int hcol = blockIdx.y * DKH;
    const size_t rowb = (size_t)blockIdx.z * SEQ;
    const uint32_t sb  = cvta_s(sm);
    const uint32_t sQh = sb, sQl = sb + FQ_B;
    const uint32_t sKV = sb + 2 * FQ_B;

    // group 0: Q (both tiles) + KV stage 0
    {
        const __nv_bfloat16* qs[2] = {Qh, Ql};
#pragma unroll
        for (int i = 0; i < 8; i++) {
            const int idx = tid + i * 256;
            const int t   = idx >> 10;
            const int rem = idx & 1023;
            const int row = rem >> 3;
            const int c   = rem & 7;
            cp16((t ? sQl : sQh) + row * FROWB + c * 16,
                 qs[t] + (rowb + q0 + row) * DIM + hcol + c * 8);
        }
    }
    ld_kv(sKV, Kh, Kl, Vh, Vl, rowb, hcol, tid);
    cp_commit();
    ld_kv(sKV + FSTG_B, Kh, Kl, Vh, Vl, rowb + 64, hcol, tid);
    cp_commit();

    float oacc[8][4];
#pragma unroll
    for (int j = 0; j < 8; j++) { oacc[j][0] = oacc[j][1] = oacc[j][2] = oacc[j][3] = 0.f; }
    float m0 = -1e30f, m1 = -1e30f, l0 = 0.f, l1 = 0.f;

    const uint32_t aoff = (uint32_t)((wid * 16 + (lane & 15)) * FROWB + ((lane >> 4) << 4));
    const uint32_t koff = (uint32_t)(((lane & 7) + ((lane >> 4) << 3)) * FROWB
                                     + ((lane & 8) ? 16 : 0));
    const uint32_t voff = (uint32_t)((lane & 15) * FROWB + ((lane >> 4) << 4));

    const int NKB = SEQ / 64;   // 32
    for (int t = 0; t < NKB; t++) {
        if (t + 1 < NKB) cp_wait1(); else cp_wait0();
        __syncthreads();
        const uint32_t st = sKV + (t & 1) * FSTG_B;

        // ---- S = (Qh+Ql)(Kh+Kl)^T x3, in log2 domain ----
        float sacc[8][4];
#pragma unroll
        for (int j = 0; j < 8; j++) { sacc[j][0] = sacc[j][1] = sacc[j][2] = sacc[j][3] = 0.f; }
#pragma unroll
        for (int kk = 0; kk < 4; kk++) {
            uint32_t ah[4], al[4];
            ldm4(ah, sQh + aoff + kk * 32);
            ldm4(al, sQl + aoff + kk * 32);
#pragma unroll
            for (int g = 0; g < 4; g++) {
                uint32_t bh[4], bl[4];
                ldm4(bh, st + koff + g * 16 * FROWB + kk * 32);
                ldm4(bl, st + FKV_T + koff + g * 16 * FROWB + kk * 32);
#pragma unroll
                for (int s = 0; s < 2; s++) {
                    float* cc = sacc[g * 2 + s];
                    mma16816(cc, ah, bh[s * 2], bh[s * 2 + 1]);
                    mma16816(cc, ah, bl[s * 2], bl[s * 2 + 1]);
                    mma16816(cc, al, bh[s * 2], bh[s * 2 + 1]);
                }
            }
        }

        // ---- online softmax (rows r = lane>>2 and r+8) ----
        float mx0 = -1e30f, mx1 = -1e30f;
#pragma unroll
        for (int j = 0; j < 8; j++) {
            mx0 = fmaxf(mx0, fmaxf(sacc[j][0], sacc[j][1]));
            mx1 = fmaxf(mx1, fmaxf(sacc[j][2], sacc[j][3]));
        }
        mx0 = fmaxf(mx0, __shfl_xor_sync(0xffffffffu, mx0, 1));
        mx0 = fmaxf(mx0, __shfl_xor_sync(0xffffffffu, mx0, 2));
        mx1 = fmaxf(mx1, __shfl_xor_sync(0xffffffffu, mx1, 1));
        mx1 = fmaxf(mx1, __shfl_xor_sync(0xffffffffu, mx1, 2));
        const float mn0 = fmaxf(m0, mx0);
        const float mn1 = fmaxf(m1, mx1);

        uint32_t ph0[8], pl0[8], ph1[8], pl1[8];
        float rs0 = 0.f, rs1 = 0.f;
#pragma unroll
        for (int j = 0; j < 8; j++) {
            const float p00 = ex2(sacc[j][0] - mn0), p01 = ex2(sacc[j][1] - mn0);
            const float p10 = ex2(sacc[j][2] - mn1), p11 = ex2(sacc[j][3] - mn1);
            rs0 += p00 + p01; rs1 += p10 + p11;
            const __nv_bfloat16 h00 = __float2bfloat16(p00), h01 = __float2bfloat16(p01);
            const __nv_bfloat16 h10 = __float2bfloat16(p10), h11 = __float2bfloat16(p11);
            ph0[j] = pack_bf2(h00, h01);
            ph1[j] = pack_bf2(h10, h11);
            pl0[j] = pack_bf2(__float2bfloat16(p00 - __bfloat162float(h00)),
                              __float2bfloat16(p01 - __bfloat162float(h01)));
            pl1[j] = pack_bf2(__float2bfloat16(p10 - __bfloat162float(h10)),
                              __float2bfloat16(p11 - __bfloat162float(h11)));
        }
        rs0 += __shfl_xor_sync(0xffffffffu, rs0, 1);
        rs0 += __shfl_xor_sync(0xffffffffu, rs0, 2);
        rs1 += __shfl_xor_sync(0xffffffffu, rs1, 1);
        rs1 += __shfl_xor_sync(0xffffffffu, rs1, 2);
        const float a0 = ex2(m0 - mn0), a1 = ex2(m1 - mn1);
        l0 = l0 * a0 + rs0;  l1 = l1 * a1 + rs1;
        m0 = mn0;  m1 = mn1;
#pragma unroll
        for (int j = 0; j < 8; j++) {
            oacc[j][0] *= a0; oacc[j][1] *= a0;
            oacc[j][2] *= a1; oacc[j][3] *= a1;
        }

        // ---- O += P @ V (x3) ----
#pragma unroll
        for (int s = 0; s < 4; s++) {
            const uint32_t aph[4] = {ph0[2*s], ph1[2*s], ph0[2*s+1], ph1[2*s+1]};
            const uint32_t apl[4] = {pl0[2*s], pl1[2*s], pl0[2*s+1], pl1[2*s+1]};
#pragma unroll
            for (int g = 0; g < 4; g++) {
                uint32_t bh4[4], bl4[4];
                ldm4t(bh4, st + 2 * FKV_T + voff + s * 16 * FROWB + g * 32);
                ldm4t(bl4, st + 3 * FKV_T + voff + s * 16 * FROWB + g * 32);
#pragma unroll
                for (int u = 0; u < 2; u++) {
                    float* cc = oacc[g * 2 + u];
                    mma16816(cc, aph, bh4[u * 2], bh4[u * 2 + 1]);
                    mma16816(cc, aph, bl4[u * 2], bl4[u * 2 + 1]);
                    mma16816(cc, apl, bh4[u * 2], bh4[u * 2 + 1]);
                }
            }
        }

        __syncthreads();
        if (t + 2 < NKB) {
            ld_kv(sKV + (t & 1) * FSTG_B, Kh, Kl, Vh, Vl,
                  rowb + (size_t)(t + 2) * 64, hcol, tid);
            cp_commit();
        }
    }

    // ---- epilogue: normalize, split to bf16 hi/lo ----
    const float inv0 = 1.f / l0, inv1 = 1.f / l1;
    const int r0 = q0 + wid * 16 + (lane >> 2);
    const int cb = hcol + (lane & 3) * 2;
#pragma unroll
    for (int j = 0; j < 8; j++) {
        const int col = cb + j * 8;
        const float v0 = oacc[j][0] * inv0, v1 = oacc[j][1] * inv0;
        const float v2 = oacc[j][2] * inv1, v3 = oacc[j][3] * inv1;
        const __nv_bfloat16 h0 = __float2bfloat16(v0), h1 = __float2bfloat16(v1);
        const __nv_bfloat16 h2 = __float2bfloat16(v2), h3 = __float2bfloat16(v3);
        *(__nv_bfloat162*)(Ch + (rowb + r0) * DIM + col)     = __halves2bfloat162(h0, h1);
        *(__nv_bfloat162*)(Ch + (rowb + r0 + 8) * DIM + col) = __halves2bfloat162(h2, h3);
        *(__nv_bfloat162*)(Cl + (rowb + r0) * DIM + col) =
            __halves2bfloat162(__float2bfloat16(v0 - __bfloat162float(h0)),
                               __float2bfloat16(v1 - __bfloat162float(h1)));
        *(__nv_bfloat162*)(Cl + (rowb + r0 + 8) * DIM + col) =
            __halves2bfloat162(__float2bfloat16(v2 - __bfloat162float(h2)),
                               __float2bfloat16(v3 - __bfloat162float(h3)));
    }
}

// ===========================================================================
// kernel_launch
// ===========================================================================
extern "C" void kernel_launch(void* const* d_in, const int* in_sizes, int n_in,
                              void* d_out, int out_size)
{
    const float* key   = (const float*)d_in[0];
    const float* query = (const float*)d_in[1];
    const float* value = (const float*)d_in[2];
    const float* Wq    = (const float*)d_in[3];
    const float* Wk    = (const float*)d_in[4];
    const float* Wv    = (const float*)d_in[5];
    const float* Wo    = (const float*)d_in[6];
    const float* bo    = (const float*)d_in[7];
    float* out = (float*)d_out;

    __nv_bfloat16 *qh, *ql, *kh, *kl, *vh, *vl, *ch, *cl;
    __nv_bfloat16 *xqh, *xql, *xkh, *xkl, *xvh, *xvl;
    __nv_bfloat16 *wqh, *wql, *wkh, *wkl, *wvh, *wvl, *woh, *wol;
    cudaGetSymbolAddress((void**)&qh, g_qh);   cudaGetSymbolAddress((void**)&ql, g_ql);
    cudaGetSymbolAddress((void**)&kh, g_kh);   cudaGetSymbolAddress((void**)&kl, g_kl);
    cudaGetSymbolAddress((void**)&vh, g_vh);   cudaGetSymbolAddress((void**)&vl, g_vl);
    cudaGetSymbolAddress((void**)&ch, g_ch);   cudaGetSymbolAddress((void**)&cl, g_cl);
    cudaGetSymbolAddress((void**)&xqh, g_xqh); cudaGetSymbolAddress((void**)&xql, g_xql);
    cudaGetSymbolAddress((void**)&xkh, g_xkh); cudaGetSymbolAddress((void**)&xkl, g_xkl);
    cudaGetSymbolAddress((void**)&xvh, g_xvh); cudaGetSymbolAddress((void**)&xvl, g_xvl);
    cudaGetSymbolAddress((void**)&wqh, g_wqh); cudaGetSymbolAddress((void**)&wql, g_wql);
    cudaGetSymbolAddress((void**)&wkh, g_wkh); cudaGetSymbolAddress((void**)&wkl, g_wkl);
    cudaGetSymbolAddress((void**)&wvh, g_wvh); cudaGetSymbolAddress((void**)&wvl, g_wvl);
    cudaGetSymbolAddress((void**)&woh, g_woh); cudaGetSymbolAddress((void**)&wol, g_wol);

    const int NB_IN = MROWS * DIM / 4 / 256;
    const int NB_W  = DIM * DIM / 4 / 256;
    split_bf16<<<NB_IN, 256>>>(query, xqh, xql);
    split_bf16<<<NB_IN, 256>>>(key,   xkh, xkl);
    split_bf16<<<NB_IN, 256>>>(value, xvh, xvl);
    split_bf16<<<NB_W, 256>>>(Wq, wqh, wql);
    split_bf16<<<NB_W, 256>>>(Wk, wkh, wkl);
    split_bf16<<<NB_W, 256>>>(Wv, wvh, wvl);
    split_bf16<<<NB_W, 256>>>(Wo, woh, wol);

    cudaFuncSetAttribute(gemm_mma_x3<0>, cudaFuncAttributeMaxDynamicSharedMemorySize, GEMM_SMEM);
    cudaFuncSetAttribute(gemm_mma_x3<1>, cudaFuncAttributeMaxDynamicSharedMemorySize, GEMM_SMEM);
    dim3 gg(DIM / 128, MROWS / 128);
    // Q scaled by 1/sqrt(dk) * log2(e) so softmax runs on raw ex2
    const float qscale = 0.125f * 1.44269504f;
    gemm_mma_x3<1><<<gg, 256, GEMM_SMEM>>>(xqh, xql, wqh, wql, nullptr, nullptr, qh, ql, qscale);
    gemm_mma_x3<1><<<gg, 256, GEMM_SMEM>>>(xkh, xkl, wkh, wkl, nullptr, nullptr, kh, kl, 1.0f);
    gemm_mma_x3<1><<<gg, 256, GEMM_SMEM>>>(xvh, xvl, wvh, wvl, nullptr, nullptr, vh, vl, 1.0f);

    cudaFuncSetAttribute(flash_mma, cudaFuncAttributeMaxDynamicSharedMemorySize, FLASH_SMEM);
    flash_mma<<<dim3(SEQ / 128, NH, BATCH), 256, FLASH_SMEM>>>(qh, ql, kh, kl, vh, vl, ch, cl);

    gemm_mma_x3<0><<<gg, 256, GEMM_SMEM>>>(ch, cl, woh, wol, bo, out, nullptr, nullptr, 1.0f);
}

// round 17
// speedup vs baseline: 1.0039x; 1.0039x over previous
#include <cuda_runtime.h>
#include <cuda_bf16.h>
#include <math.h>
#include <stdint.h>

#define BATCH 2
#define SEQ   2048
#define DIM   1024
#define NH    16
#define DKH   64
#define MROWS (BATCH*SEQ)

// ---- scratch (allocation-free rules): bf16 hi/lo split buffers ----
__device__ __nv_bfloat16 g_qh[MROWS * DIM], g_ql[MROWS * DIM];
__device__ __nv_bfloat16 g_kh[MROWS * DIM], g_kl[MROWS * DIM];
__device__ __nv_bfloat16 g_vh[MROWS * DIM], g_vl[MROWS * DIM];
__device__ __nv_bfloat16 g_ch[MROWS * DIM], g_cl[MROWS * DIM];
__device__ __nv_bfloat16 g_xqh[MROWS * DIM], g_xql[MROWS * DIM];  // input splits
__device__ __nv_bfloat16 g_xkh[MROWS * DIM], g_xkl[MROWS * DIM];
__device__ __nv_bfloat16 g_xvh[MROWS * DIM], g_xvl[MROWS * DIM];
__device__ __nv_bfloat16 g_wqh[DIM * DIM], g_wql[DIM * DIM];
__device__ __nv_bfloat16 g_wkh[DIM * DIM], g_wkl[DIM * DIM];
__device__ __nv_bfloat16 g_wvh[DIM * DIM], g_wvl[DIM * DIM];
__device__ __nv_bfloat16 g_woh[DIM * DIM], g_wol[DIM * DIM];

// ===========================================================================
// Baseline-PTX helpers (sm_80+)
// ===========================================================================
__device__ __forceinline__ uint32_t cvta_s(const void* p) {
    uint32_t a;
    asm("{ .reg .u64 t; cvta.to.shared.u64 t, %1; cvt.u32.u64 %0, t; }"
        : "=r"(a) : "l"(p));
    return a;
}
__device__ __forceinline__ void ldm4(uint32_t* r, uint32_t addr) {
    asm volatile("ldmatrix.sync.aligned.m8n8.x4.shared.b16 {%0,%1,%2,%3},[%4];"
        : "=r"(r[0]), "=r"(r[1]), "=r"(r[2]), "=r"(r[3]) : "r"(addr));
}
__device__ __forceinline__ void ldm4t(uint32_t* r, uint32_t addr) {
    asm volatile("ldmatrix.sync.aligned.m8n8.x4.trans.shared.b16 {%0,%1,%2,%3},[%4];"
        : "=r"(r[0]), "=r"(r[1]), "=r"(r[2]), "=r"(r[3]) : "r"(addr));
}
__device__ __forceinline__ void mma16816(float* c, const uint32_t* a,
                                         uint32_t b0, uint32_t b1) {
    asm volatile(
        "mma.sync.aligned.m16n8k16.row.col.f32.bf16.bf16.f32 "
        "{%0,%1,%2,%3},{%4,%5,%6,%7},{%8,%9},{%0,%1,%2,%3};"
        : "+f"(c[0]), "+f"(c[1]), "+f"(c[2]), "+f"(c[3])
        : "r"(a[0]), "r"(a[1]), "r"(a[2]), "r"(a[3]), "r"(b0), "r"(b1));
}
__device__ __forceinline__ void cp16(uint32_t dst, const void* src) {
    asm volatile("cp.async.cg.shared.global [%0], [%1], 16;"
        :: "r"(dst), "l"(src) : "memory");
}
__device__ __forceinline__ void cp_commit() {
    asm volatile("cp.async.commit_group;" ::: "memory");
}
__device__ __forceinline__ void cp_wait0() {
    asm volatile("cp.async.wait_group 0;" ::: "memory");
}
__device__ __forceinline__ void cp_wait1() {
    asm volatile("cp.async.wait_group 1;" ::: "memory");
}
__device__ __forceinline__ float ex2(float x) {
    float y;
    asm("ex2.approx.ftz.f32 %0, %1;" : "=f"(y) : "f"(x));
    return y;
}
__device__ __forceinline__ uint32_t pack_bf2(__nv_bfloat16 a, __nv_bfloat16 b) {
    __nv_bfloat162 t = __halves2bfloat162(a, b);
    return reinterpret_cast<uint32_t&>(t);
}

// ===========================================================================
// Split fp32 -> (bf16 hi, bf16 lo)
// ===========================================================================
__global__ __launch_bounds__(256) void split_bf16(
    const float* __restrict__ x, __nv_bfloat16* __restrict__ hi,
    __nv_bfloat16* __restrict__ lo)
{
    const int i = blockIdx.x * 256 + threadIdx.x;
    float4 v = ((const float4*)x)[i];
    __nv_bfloat16 h0 = __float2bfloat16(v.x);
    __nv_bfloat16 h1 = __float2bfloat16(v.y);
    __nv_bfloat16 h2 = __float2bfloat16(v.z);
    __nv_bfloat16 h3 = __float2bfloat16(v.w);
    __nv_bfloat16 l0 = __float2bfloat16(v.x - __bfloat162float(h0));
    __nv_bfloat16 l1 = __float2bfloat16(v.y - __bfloat162float(h1));
    __nv_bfloat16 l2 = __float2bfloat16(v.z - __bfloat162float(h2));
    __nv_bfloat16 l3 = __float2bfloat16(v.w - __bfloat162float(h3));
    ((__nv_bfloat162*)hi)[i * 2 + 0] = __halves2bfloat162(h0, h1);
    ((__nv_bfloat162*)hi)[i * 2 + 1] = __halves2bfloat162(h2, h3);
    ((__nv_bfloat162*)lo)[i * 2 + 0] = __halves2bfloat162(l0, l1);
    ((__nv_bfloat162*)lo)[i * 2 + 1] = __halves2bfloat162(l2, l3);
}

// ===========================================================================
// GEMM (NT) via mma.sync bf16 split-x3:  C = A @ W^T
// MODE 0: fp32 out + bias.  MODE 1: scaled bf16 hi/lo split out.
// ===========================================================================
#define ROWB   80
#define TILE_B (128*ROWB)
#define STAGE_B (4*TILE_B)
#define GEMM_SMEM (2*STAGE_B)

__device__ __forceinline__ void ld_stage(
    uint32_t sdst, const __nv_bfloat16* __restrict__ Ah,
    const __nv_bfloat16* __restrict__ Al,
    const __nv_bfloat16* __restrict__ Wh,
    const __nv_bfloat16* __restrict__ Wl,
    int m0, int n0, int kb, int tid)
{
    const int r_lo = tid >> 2;
    const int c    = tid & 3;
    const __nv_bfloat16* gsrc[4] = {Ah, Al, Wh, Wl};
    const int rbase[4] = {m0, m0, n0, n0};
#pragma unroll
    for (int t = 0; t < 4; t++) {
#pragma unroll
        for (int half = 0; half < 2; half++) {
            const int r = r_lo + half * 64;
            cp16(sdst + t * TILE_B + r * ROWB + c * 16,
                 gsrc[t] + (size_t)(rbase[t] + r) * DIM + kb + c * 8);
        }
    }
}

template <int MODE>
__global__ __launch_bounds__(256) void gemm_mma_x3(
    const __nv_bfloat16* __restrict__ Ah, const __nv_bfloat16* __restrict__ Al,
    const __nv_bfloat16* __restrict__ Wh, const __nv_bfloat16* __restrict__ Wl,
    const float* __restrict__ bias, float* __restrict__ Cc,
    __nv_bfloat16* __restrict__ Oh, __nv_bfloat16* __restrict__ Ol, float scale)
{
    extern __shared__ __align__(128) char sm[];
    const int tid  = threadIdx.x;
    const int lane = tid & 31;
    const int wid  = tid >> 5;
    const int wm   = wid & 3;
    const int wn   = wid >> 2;
    const int m0 = blockIdx.y * 128;
    const int n0 = blockIdx.x * 128;
    const uint32_t sb = cvta_s(sm);

    float acc[2][8][4];
#pragma unroll
    for (int m = 0; m < 2; m++)
#pragma unroll
        for (int n = 0; n < 8; n++)
#pragma unroll
            for (int j = 0; j < 4; j++) acc[m][n][j] = 0.f;

    const uint32_t aOff = (uint32_t)((wm * 32 + (lane & 15)) * ROWB + ((lane >> 4) << 4));
    const uint32_t bOff = (uint32_t)((wn * 64 + (lane & 7) + ((lane >> 4) << 3)) * ROWB
                                     + ((lane & 8) ? 16 : 0));

    ld_stage(sb, Ah, Al, Wh, Wl, m0, n0, 0, tid);
    cp_commit();

    const int NST = DIM / 32;
    for (int t = 0; t < NST; t++) {
        cp_wait0();
        __syncthreads();
        if (t + 1 < NST) {
            ld_stage(sb + ((t + 1) & 1) * STAGE_B, Ah, Al, Wh, Wl,
                     m0, n0, (t + 1) * 32, tid);
            cp_commit();
        }
        const uint32_t st = sb + (t & 1) * STAGE_B;

#pragma unroll
        for (int kk = 0; kk < 2; kk++) {
            const uint32_t kByte = kk * 32;
            uint32_t ah[2][4], al[2][4];
#pragma unroll
            for (int mf = 0; mf < 2; mf++) {
                ldm4(ah[mf], st + aOff + mf * 16 * ROWB + kByte);
                ldm4(al[mf], st + TILE_B + aOff + mf * 16 * ROWB + kByte);
            }
            uint32_t bh[4][4], bl[4][4];
#pragma unroll
            for (int g = 0; g < 4; g++) {
                ldm4(bh[g], st + 2 * TILE_B + bOff + g * 16 * ROWB + kByte);
                ldm4(bl[g], st + 3 * TILE_B + bOff + g * 16 * ROWB + kByte);
            }
#pragma unroll
            for (int mf = 0; mf < 2; mf++)
#pragma unroll
                for (int g = 0; g < 4; g++)
#pragma unroll
                    for (int s = 0; s < 2; s++) {
                        float* cc = acc[mf][g * 2 + s];
                        mma16816(cc, ah[mf], bh[g][s * 2], bh[g][s * 2 + 1]);
                        mma16816(cc, ah[mf], bl[g][s * 2], bl[g][s * 2 + 1]);
                        mma16816(cc, al[mf], bh[g][s * 2], bh[g][s * 2 + 1]);
                    }
        }
        __syncthreads();
    }

    const int grp = lane >> 2;
    const int tig = lane & 3;
#pragma unroll
    for (int mf = 0; mf < 2; mf++) {
        const int row = m0 + wm * 32 + mf * 16 + grp;
#pragma unroll
        for (int n8 = 0; n8 < 8; n8++) {
            const int col = n0 + wn * 64 + n8 * 8 + tig * 2;
            if (MODE == 0) {
                float2 v0 = make_float2(acc[mf][n8][0], acc[mf][n8][1]);
                float2 v1 = make_float2(acc[mf][n8][2], acc[mf][n8][3]);
                const float2 b = *(const float2*)(bias + col);
                v0.x += b.x; v0.y += b.y; v1.x += b.x; v1.y += b.y;
                *(float2*)(Cc + (size_t)row * DIM + col)       = v0;
                *(float2*)(Cc + (size_t)(row + 8) * DIM + col) = v1;
            } else {
                const float v0 = acc[mf][n8][0] * scale, v1 = acc[mf][n8][1] * scale;
                const float v2 = acc[mf][n8][2] * scale, v3 = acc[mf][n8][3] * scale;
                __nv_bfloat16 h0 = __float2bfloat16(v0), h1 = __float2bfloat16(v1);
                __nv_bfloat16 h2 = __float2bfloat16(v2), h3 = __float2bfloat16(v3);
                __nv_bfloat16 e0 = __float2bfloat16(v0 - __bfloat162float(h0));
                __nv_bfloat16 e1 = __float2bfloat16(v1 - __bfloat162float(h1));
                __nv_bfloat16 e2 = __float2bfloat16(v2 - __bfloat162float(h2));
                __nv_bfloat16 e3 = __float2bfloat16(v3 - __bfloat162float(h3));
                *(__nv_bfloat162*)(Oh + (size_t)row * DIM + col)       = __halves2bfloat162(h0, h1);
                *(__nv_bfloat162*)(Oh + (size_t)(row + 8) * DIM + col) = __halves2bfloat162(h2, h3);
                *(__nv_bfloat162*)(Ol + (size_t)row * DIM + col)       = __halves2bfloat162(e0, e1);
                *(__nv_bfloat162*)(Ol + (size_t)(row + 8) * DIM + col) = __halves2bfloat162(e2, e3);
            }
        }
    }
}

// ===========================================================================
// Flash attention via mma.sync bf16 split-x3 (FA2 register P-reuse).
// CTA: 128 q rows x one (b,h); 8 warps, each owns 16 q rows x full 64-key tile.
// KV tiles of 64 keys, cp.async double-buffered. Scores in log2 domain.
// ===========================================================================
#define FROWB 144                       // 72 bf16 per row (64 data + 8 pad)
#define FQ_B   (128*FROWB)              // 18432
#define FKV_T  (64*FROWB)               // 9216
#define FSTG_B (4*FKV_T)                // 36864
#define FLASH_SMEM (2*FQ_B + 2*FSTG_B)  // 110592

__device__ __forceinline__ void ld_kv(
    uint32_t dst, const __nv_bfloat16* __restrict__ Kh,
    const __nv_bfloat16* __restrict__ Kl,
    const __nv_bfloat16* __restrict__ Vh,
    const __nv_bfloat16* __restrict__ Vl,
    size_t grow, int hcol, int tid)
{
    const __nv_bfloat16* srcs[4] = {Kh, Kl, Vh, Vl};
#pragma unroll
    for (int i = 0; i < 8; i++) {
        const int idx = tid + i * 256;
        const int t   = idx >> 9;
        const int rem = idx & 511;
        const int row = rem >> 3;
        const int c   = rem & 7;
        cp16(dst + t * FKV_T + row * FROWB + c * 16,
             srcs[t] + (grow + row) * DIM + hcol + c * 8);
    }
}

__global__ __launch_bounds__(256) void flash_mma(
    const __nv_bfloat16* __restrict__ Qh, const __nv_bfloat16* __restrict__ Ql,
    const __nv_bfloat16* __restrict__ Kh, const __nv_bfloat16* __restrict__ Kl,
    const __nv_bfloat16* __restrict__ Vh, const __nv_bfloat16* __restrict__ Vl,
    __nv_bfloat16* __restrict__ Ch, __nv_bfloat16* __restrict__ Cl)
{
    extern __shared__ __align__(128) char sm[];
    const int tid  = threadIdx.x;
    const int lane = tid & 31;
    const int wid  = tid >> 5;
    const int q0   = blockIdx.x * 128;
    const int hcol = blockIdx.y * DKH;
    const size_t rowb = (size_t)blockIdx.z * SEQ;
    const uint32_t sb  = cvta_s(sm);
    const uint32_t sQh = sb, sQl = sb + FQ_B;
    const uint32_t sKV = sb + 2 * FQ_B;

    // group 0: Q (both tiles) + KV stage 0
    {
        const __nv_bfloat16* qs[2] = {Qh, Ql};
#pragma unroll
        for (int i = 0; i < 8; i++) {
            const int idx = tid + i * 256;
            const int t   = idx >> 10;
            const int rem = idx & 1023;
            const int row = rem >> 3;
            const int c   = rem & 7;
            cp16((t ? sQl : sQh) + row * FROWB + c * 16,
                 qs[t] + (rowb + q0 + row) * DIM + hcol + c * 8);
        }
    }
    ld_kv(sKV, Kh, Kl, Vh, Vl, rowb, hcol, tid);
    cp_commit();
    ld_kv(sKV + FSTG_B, Kh, Kl, Vh, Vl, rowb + 64, hcol, tid);
    cp_commit();

    float oacc[8][4];
#pragma unroll
    for (int j = 0; j < 8; j++) { oacc[j][0] = oacc[j][1] = oacc[j][2] = oacc[j][3] = 0.f; }
    float m0 = -1e30f, m1 = -1e30f, l0 = 0.f, l1 = 0.f;

    const uint32_t aoff = (uint32_t)((wid * 16 + (lane & 15)) * FROWB + ((lane >> 4) << 4));
    const uint32_t koff = (uint32_t)(((lane & 7) + ((lane >> 4) << 3)) * FROWB
                                     + ((lane & 8) ? 16 : 0));
    const uint32_t voff = (uint32_t)((lane & 15) * FROWB + ((lane >> 4) << 4));

    const int NKB = SEQ / 64;   // 32
    for (int t = 0; t < NKB; t++) {
        if (t + 1 < NKB) cp_wait1(); else cp_wait0();
        __syncthreads();
        const uint32_t st = sKV + (t & 1) * FSTG_B;

        // ---- S = (Qh+Ql)(Kh+Kl)^T x3, in log2 domain ----
        float sacc[8][4];
#pragma unroll
        for (int j = 0; j < 8; j++) { sacc[j][0] = sacc[j][1] = sacc[j][2] = sacc[j][3] = 0.f; }
#pragma unroll
        for (int kk = 0; kk < 4; kk++) {
            uint32_t ah[4], al[4];
            ldm4(ah, sQh + aoff + kk * 32);
            ldm4(al, sQl + aoff + kk * 32);
#pragma unroll
            for (int g = 0; g < 4; g++) {
                uint32_t bh[4], bl[4];
                ldm4(bh, st + koff + g * 16 * FROWB + kk * 32);
                ldm4(bl, st + FKV_T + koff + g * 16 * FROWB + kk * 32);
#pragma unroll
                for (int s = 0; s < 2; s++) {
                    float* cc = sacc[g * 2 + s];
                    mma16816(cc, ah, bh[s * 2], bh[s * 2 + 1]);
                    mma16816(cc, ah, bl[s * 2], bl[s * 2 + 1]);
                    mma16816(cc, al, bh[s * 2], bh[s * 2 + 1]);
                }
            }
        }

        // ---- online softmax (rows r = lane>>2 and r+8) ----
        float mx0 = -1e30f, mx1 = -1e30f;
#pragma unroll
        for (int j = 0; j < 8; j++) {
            mx0 = fmaxf(mx0, fmaxf(sacc[j][0], sacc[j][1]));
            mx1 = fmaxf(mx1, fmaxf(sacc[j][2], sacc[j][3]));
        }
        mx0 = fmaxf(mx0, __shfl_xor_sync(0xffffffffu, mx0, 1));
        mx0 = fmaxf(mx0, __shfl_xor_sync(0xffffffffu, mx0, 2));
        mx1 = fmaxf(mx1, __shfl_xor_sync(0xffffffffu, mx1, 1));
        mx1 = fmaxf(mx1, __shfl_xor_sync(0xffffffffu, mx1, 2));
        const float mn0 = fmaxf(m0, mx0);
        const float mn1 = fmaxf(m1, mx1);

        uint32_t ph0[8], pl0[8], ph1[8], pl1[8];
        float rs0 = 0.f, rs1 = 0.f;
#pragma unroll
        for (int j = 0; j < 8; j++) {
            const float p00 = ex2(sacc[j][0] - mn0), p01 = ex2(sacc[j][1] - mn0);
            const float p10 = ex2(sacc[j][2] - mn1), p11 = ex2(sacc[j][3] - mn1);
            rs0 += p00 + p01; rs1 += p10 + p11;
            const __nv_bfloat16 h00 = __float2bfloat16(p00), h01 = __float2bfloat16(p01);
            const __nv_bfloat16 h10 = __float2bfloat16(p10), h11 = __float2bfloat16(p11);
            ph0[j] = pack_bf2(h00, h01);
            ph1[j] = pack_bf2(h10, h11);
            pl0[j] = pack_bf2(__float2bfloat16(p00 - __bfloat162float(h00)),
                              __float2bfloat16(p01 - __bfloat162float(h01)));
            pl1[j] = pack_bf2(__float2bfloat16(p10 - __bfloat162float(h10)),
                              __float2bfloat16(p11 - __bfloat162float(h11)));
        }
        rs0 += __shfl_xor_sync(0xffffffffu, rs0, 1);
        rs0 += __shfl_xor_sync(0xffffffffu, rs0, 2);
        rs1 += __shfl_xor_sync(0xffffffffu, rs1, 1);
        rs1 += __shfl_xor_sync(0xffffffffu, rs1, 2);
        const float a0 = ex2(m0 - mn0), a1 = ex2(m1 - mn1);
        l0 = l0 * a0 + rs0;  l1 = l1 * a1 + rs1;
        m0 = mn0;  m1 = mn1;
#pragma unroll
        for (int j = 0; j < 8; j++) {
            oacc[j][0] *= a0; oacc[j][1] *= a0;
            oacc[j][2] *= a1; oacc[j][3] *= a1;
        }

        // ---- O += P @ V (x3) ----
#pragma unroll
        for (int s = 0; s < 4; s++) {
            const uint32_t aph[4] = {ph0[2*s], ph1[2*s], ph0[2*s+1], ph1[2*s+1]};
            const uint32_t apl[4] = {pl0[2*s], pl1[2*s], pl0[2*s+1], pl1[2*s+1]};
#pragma unroll
            for (int g = 0; g < 4; g++) {
                uint32_t bh4[4], bl4[4];
                ldm4t(bh4, st + 2 * FKV_T + voff + s * 16 * FROWB + g * 32);
                ldm4t(bl4, st + 3 * FKV_T + voff + s * 16 * FROWB + g * 32);
#pragma unroll
                for (int u = 0; u < 2; u++) {
                    float* cc = oacc[g * 2 + u];
                    mma16816(cc, aph, bh4[u * 2], bh4[u * 2 + 1]);
                    mma16816(cc, aph, bl4[u * 2], bl4[u * 2 + 1]);
                    mma16816(cc, apl, bh4[u * 2], bh4[u * 2 + 1]);
                }
            }
        }

        __syncthreads();
        if (t + 2 < NKB) {
            ld_kv(sKV + (t & 1) * FSTG_B, Kh, Kl, Vh, Vl,
                  rowb + (size_t)(t + 2) * 64, hcol, tid);
            cp_commit();
        }
    }

    // ---- epilogue: normalize, split to bf16 hi/lo ----
    const float inv0 = 1.f / l0, inv1 = 1.f / l1;
    const int r0 = q0 + wid * 16 + (lane >> 2);
    const int cb = hcol + (lane & 3) * 2;
#pragma unroll
    for (int j = 0; j < 8; j++) {
        const int col = cb + j * 8;
        const float v0 = oacc[j][0] * inv0, v1 = oacc[j][1] * inv0;
        const float v2 = oacc[j][2] * inv1, v3 = oacc[j][3] * inv1;
        const __nv_bfloat16 h0 = __float2bfloat16(v0), h1 = __float2bfloat16(v1);
        const __nv_bfloat16 h2 = __float2bfloat16(v2), h3 = __float2bfloat16(v3);
        *(__nv_bfloat162*)(Ch + (rowb + r0) * DIM + col)     = __halves2bfloat162(h0, h1);
        *(__nv_bfloat162*)(Ch + (rowb + r0 + 8) * DIM + col) = __halves2bfloat162(h2, h3);
        *(__nv_bfloat162*)(Cl + (rowb + r0) * DIM + col) =
            __halves2bfloat162(__float2bfloat16(v0 - __bfloat162float(h0)),
                               __float2bfloat16(v1 - __bfloat162float(h1)));
        *(__nv_bfloat162*)(Cl + (rowb + r0 + 8) * DIM + col) =
            __halves2bfloat162(__float2bfloat16(v2 - __bfloat162float(h2)),
                               __float2bfloat16(v3 - __bfloat162float(h3)));
    }
}

// ===========================================================================
// kernel_launch
// ===========================================================================
extern "C" void kernel_launch(void* const* d_in, const int* in_sizes, int n_in,
                              void* d_out, int out_size)
{
    const float* key   = (const float*)d_in[0];
    const float* query = (const float*)d_in[1];
    const float* value = (const float*)d_in[2];
    const float* Wq    = (const float*)d_in[3];
    const float* Wk    = (const float*)d_in[4];
    const float* Wv    = (const float*)d_in[5];
    const float* Wo    = (const float*)d_in[6];
    const float* bo    = (const float*)d_in[7];
    float* out = (float*)d_out;

    __nv_bfloat16 *qh, *ql, *kh, *kl, *vh, *vl, *ch, *cl;
    __nv_bfloat16 *xqh, *xql, *xkh, *xkl, *xvh, *xvl;
    __nv_bfloat16 *wqh, *wql, *wkh, *wkl, *wvh, *wvl, *woh, *wol;
    cudaGetSymbolAddress((void**)&qh, g_qh);   cudaGetSymbolAddress((void**)&ql, g_ql);
    cudaGetSymbolAddress((void**)&kh, g_kh);   cudaGetSymbolAddress((void**)&kl, g_kl);
    cudaGetSymbolAddress((void**)&vh, g_vh);   cudaGetSymbolAddress((void**)&vl, g_vl);
    cudaGetSymbolAddress((void**)&ch, g_ch);   cudaGetSymbolAddress((void**)&cl, g_cl);
    cudaGetSymbolAddress((void**)&xqh, g_xqh); cudaGetSymbolAddress((void**)&xql, g_xql);
    cudaGetSymbolAddress((void**)&xkh, g_xkh); cudaGetSymbolAddress((void**)&xkl, g_xkl);
    cudaGetSymbolAddress((void**)&xvh, g_xvh); cudaGetSymbolAddress((void**)&xvl, g_xvl);
    cudaGetSymbolAddress((void**)&wqh, g_wqh); cudaGetSymbolAddress((void**)&wql, g_wql);
    cudaGetSymbolAddress((void**)&wkh, g_wkh); cudaGetSymbolAddress((void**)&wkl, g_wkl);
    cudaGetSymbolAddress((void**)&wvh, g_wvh); cudaGetSymbolAddress((void**)&wvl, g_wvl);
    cudaGetSymbolAddress((void**)&woh, g_woh); cudaGetSymbolAddress((void**)&wol, g_wol);

    const int NB_IN = MROWS * DIM / 4 / 256;
    const int NB_W  = DIM * DIM / 4 / 256;
    split_bf16<<<NB_IN, 256>>>(query, xqh, xql);
    split_bf16<<<NB_IN, 256>>>(key,   xkh, xkl);
    split_bf16<<<NB_IN, 256>>>(value, xvh, xvl);
    split_bf16<<<NB_W, 256>>>(Wq, wqh, wql);
    split_bf16<<<NB_W, 256>>>(Wk, wkh, wkl);
    split_bf16<<<NB_W, 256>>>(Wv, wvh, wvl);
    split_bf16<<<NB_W, 256>>>(Wo, woh, wol);

    cudaFuncSetAttribute(gemm_mma_x3<0>, cudaFuncAttributeMaxDynamicSharedMemorySize, GEMM_SMEM);
    cudaFuncSetAttribute(gemm_mma_x3<1>, cudaFuncAttributeMaxDynamicSharedMemorySize, GEMM_SMEM);
    dim3 gg(DIM / 128, MROWS / 128);
    // Q scaled by 1/sqrt(dk) * log2(e) so softmax runs on raw ex2
    const float qscale = 0.125f * 1.44269504f;
    gemm_mma_x3<1><<<gg, 256, GEMM_SMEM>>>(xqh, xql, wqh, wql, nullptr, nullptr, qh, ql, qscale);
    gemm_mma_x3<1><<<gg, 256, GEMM_SMEM>>>(xkh, xkl, wkh, wkl, nullptr, nullptr, kh, kl, 1.0f);
    gemm_mma_x3<1><<<gg, 256, GEMM_SMEM>>>(xvh, xvl, wvh, wvl, nullptr, nullptr, vh, vl, 1.0f);

    cudaFuncSetAttribute(flash_mma, cudaFuncAttributeMaxDynamicSharedMemorySize, FLASH_SMEM);
    flash_mma<<<dim3(SEQ / 128, NH, BATCH), 256, FLASH_SMEM>>>(qh, ql, kh, kl, vh, vl, ch, cl);

    gemm_mma_x3<0><<<gg, 256, GEMM_SMEM>>>(ch, cl, woh, wol, bo, out, nullptr, nullptr, 1.0f);
}